// round 10
// baseline (speedup 1.0000x reference)
#include <cuda_runtime.h>
#include <stdint.h>
#include <math.h>

#define BB 16
#define NL 48
#define NP 256
#define DD 128
#define NROW_L (BB*NL)    /* 768  */
#define NROW_P (BB*NP)    /* 4096 */
#define NPAIR  (BB*NL*NP) /* 196608 */

#define PI_OFF 0
#define SG_OFF (NPAIR*10)
#define MU_OFF (NPAIR*20)
#define DI_OFF (NPAIR*30)
#define CM_OFF (NPAIR*31)

// dynamic smem layout for k_main (one-l Csm => 3 blocks/SM)
#define CPAD 34
#define SM_UEU   0                        /* float2[256]        2048 B  */
#define SM_BS    2048                     /* uint2[2048]       16384 B  */
#define SM_CSM   (2048+16384)             /* float[256*34]     34816 B  */
#define SM_BIAS  (2048+16384+34816)       /* float[32]           128 B  */
#define SM_TOTAL (2048+16384+34816+128)   /* 53376 B */

__device__ float2 g_ueu[NROW_L*DD];   // {u, exp(u)} per (b,l,d)
__device__ float2 g_w  [BB*DD*NP];    // [b][d][p] {v, exp(v)}
__device__ float4 g_xl [NROW_L];      // x,y,z,|x|^2 (zeros if masked)
__device__ float4 g_xp [NROW_P];

__device__ __forceinline__ uint32_t cvt_tf32(float f) {
    uint32_t r;
    asm("cvt.rna.tf32.f32 %0, %1;" : "=r"(r) : "f"(f));
    return r;
}
__device__ __forceinline__ void mma8(float* c, const uint32_t* a, const uint32_t* b) {
    asm("mma.sync.aligned.m16n8k8.row.col.f32.tf32.tf32.f32 "
        "{%0,%1,%2,%3}, {%4,%5,%6,%7}, {%8,%9}, {%0,%1,%2,%3};"
        : "+f"(c[0]), "+f"(c[1]), "+f"(c[2]), "+f"(c[3])
        : "r"(a[0]), "r"(a[1]), "r"(a[2]), "r"(a[3]), "r"(b[0]), "r"(b[1]));
}
__device__ __forceinline__ float elu2(float2 u, float2 w) {
    float uv = u.x + w.x;
    float t  = fmaf(u.y, w.y, -1.f);
    return (uv > 0.f) ? uv : t;
}

// ---------------- fused prep (unchanged) ----------------
__global__ __launch_bounds__(DD) void k_pre(
    const float* __restrict__ hl, const float* __restrict__ hp,
    const float* __restrict__ pos_l, const float* __restrict__ pos_p,
    const int* __restrict__ num_l, const int* __restrict__ num_p,
    const float* __restrict__ W1, const float* __restrict__ b1,
    const float* __restrict__ gamma, const float* __restrict__ beta,
    const float* __restrict__ mean, const float* __restrict__ var)
{
    __shared__ int cl[BB+1], cp[BB+1];
    __shared__ float xs[8][DD];
    __shared__ float2 tt[DD][9];
    const int tid = threadIdx.x;

    if (tid == 0) {
        cl[0] = 0; cp[0] = 0;
        #pragma unroll
        for (int i = 0; i < BB; i++) { cl[i+1] = cl[i] + num_l[i]; cp[i+1] = cp[i] + num_p[i]; }
    }
    __syncthreads();

    const float kf = gamma[tid] * rsqrtf(var[tid] + 1e-5f);

    if (blockIdx.x < NROW_L/8) {
        const int r0 = blockIdx.x * 8;
        const int b  = r0 / NL, l0 = r0 % NL;
        const int nl = num_l[b];
        #pragma unroll
        for (int i = 0; i < 8; i++) {
            float v = 0.f;
            if (l0 + i < nl) v = hl[(cl[b] + l0 + i) * DD + tid];
            xs[i][tid] = v;
        }
        __syncthreads();
        float acc[8] = {0,0,0,0,0,0,0,0};
        #pragma unroll 4
        for (int d = 0; d < DD; d++) {
            float w = W1[d * DD + tid];
            #pragma unroll
            for (int i = 0; i < 8; i++) acc[i] = fmaf(xs[i][d], w, acc[i]);
        }
        const float c = (b1[tid] - mean[tid]) * kf + beta[tid];
        #pragma unroll
        for (int i = 0; i < 8; i++) {
            float u = fmaf(acc[i], kf, c);
            g_ueu[(r0 + i) * DD + tid] = make_float2(u, __expf(u));
        }
        if (tid < 8) {
            int l = l0 + tid;
            float4 o = make_float4(0.f, 0.f, 0.f, 0.f);
            if (l < nl) {
                int s = cl[b] + l;
                float x = pos_l[s*3+0], y = pos_l[s*3+1], z = pos_l[s*3+2];
                o = make_float4(x, y, z, x*x + y*y + z*z);
            }
            g_xl[r0 + tid] = o;
        }
    } else {
        const int r0 = (blockIdx.x - NROW_L/8) * 8;
        const int b  = r0 / NP, p0 = r0 % NP;
        const int np = num_p[b];
        #pragma unroll
        for (int i = 0; i < 8; i++) {
            float v = 0.f;
            if (p0 + i < np) v = hp[(cp[b] + p0 + i) * DD + tid];
            xs[i][tid] = v;
        }
        __syncthreads();
        float acc[8] = {0,0,0,0,0,0,0,0};
        const float* W1b = W1 + DD * DD;
        #pragma unroll 4
        for (int d = 0; d < DD; d++) {
            float w = W1b[d * DD + tid];
            #pragma unroll
            for (int i = 0; i < 8; i++) acc[i] = fmaf(xs[i][d], w, acc[i]);
        }
        #pragma unroll
        for (int i = 0; i < 8; i++) {
            float v = acc[i] * kf;
            tt[tid][i] = make_float2(v, __expf(v));
        }
        __syncthreads();
        #pragma unroll
        for (int it = 0; it < 8; it++) {
            int idx = tid + DD * it;
            int f = idx >> 3, pl = idx & 7;
            g_w[(b * DD + f) * NP + p0 + pl] = tt[f][pl];
        }
        if (tid < 8) {
            int p = p0 + tid;
            float4 o = make_float4(0.f, 0.f, 0.f, 0.f);
            if (p < np) {
                int s = cp[b] + p;
                float x = pos_p[s*3+0], y = pos_p[s*3+1], z = pos_p[s*3+2];
                o = make_float4(x, y, z, x*x + y*y + z*z);
            }
            g_xp[r0 + tid] = o;
        }
    }
}

// ---------------- epilogue for one l-row (reads Csm), per-p ----------------
__device__ __forceinline__ void epi_l(
    const float* __restrict__ Csm, const float* __restrict__ bias,
    int bl, int p, float m, float4 xp, float4 xl, float* __restrict__ out)
{
    const float* row = &Csm[p * CPAD];
    float z[30];
    #pragma unroll
    for (int jj = 0; jj < 15; jj++) {
        float2 q = *(const float2*)&row[2*jj];
        z[2*jj] = q.x; z[2*jj+1] = q.y;
    }

    float zmax = -1e30f;
    #pragma unroll
    for (int j = 0; j < 10; j++) { z[j] += bias[j]; zmax = fmaxf(zmax, z[j]); }
    float ssum = 0.f;
    #pragma unroll
    for (int j = 0; j < 10; j++) { float e = __expf(z[j] - zmax); z[j] = e; ssum += e; }
    float inv = m / ssum;

    const int base = (bl * NP + p) * 10;
    float2* opi = (float2*)(out + PI_OFF + base);
    float2* osg = (float2*)(out + SG_OFF + base);
    float2* omu = (float2*)(out + MU_OFF + base);
    #pragma unroll
    for (int j = 0; j < 5; j++)
        opi[j] = make_float2(z[2*j] * inv, z[2*j+1] * inv);
    #pragma unroll
    for (int j = 0; j < 10; j++) {
        float t = z[10 + j] + bias[10 + j];
        float e = (t > 0.f) ? t : (__expf(t) - 1.f);
        z[10 + j] = (e + 1.1f) * m;
    }
    #pragma unroll
    for (int j = 0; j < 5; j++) osg[j] = make_float2(z[10+2*j], z[11+2*j]);
    #pragma unroll
    for (int j = 0; j < 10; j++) {
        float t = z[20 + j] + bias[20 + j];
        float e = (t > 0.f) ? t : (__expf(t) - 1.f);
        z[20 + j] = (e + 1.0f) * m;
    }
    #pragma unroll
    for (int j = 0; j < 5; j++) omu[j] = make_float2(z[20+2*j], z[21+2*j]);

    float d2 = xl.w + xp.w - 2.f * (xl.x*xp.x + xl.y*xp.y + xl.z*xp.z);
    out[DI_OFF + bl * NP + p] = sqrtf(fmaxf(d2, 0.f)) * m;
    out[CM_OFF + bl * NP + p] = m;
}

// ---------------- main: tf32 MMA, 2 l-rows per block, 3 blocks/SM ----------------
__global__ __launch_bounds__(256, 3) void k_main(
    const float* __restrict__ W_pi, const float* __restrict__ b_pi,
    const float* __restrict__ W_sg, const float* __restrict__ b_sg,
    const float* __restrict__ W_mu, const float* __restrict__ b_mu,
    const int* __restrict__ num_l, const int* __restrict__ num_p,
    float* __restrict__ out)
{
    extern __shared__ char smem[];
    float2* ueu_s = (float2*)(smem + SM_UEU);
    uint2*  Bs    = (uint2*)(smem + SM_BS);
    float*  Csm   = (float*)(smem + SM_CSM);   // [256][CPAD] — one l at a time
    float*  bias  = (float*)(smem + SM_BIAS);

    const int tid = threadIdx.x;
    const int bl0 = blockIdx.x * 2;
    const int b   = bl0 / NL;
    const int l0  = bl0 % NL;

    ueu_s[tid] = g_ueu[bl0 * DD + tid];

    for (int s = tid; s < 2048; s += 256) {
        int lane_s = s & 31, nt = (s >> 5) & 3, ks = s >> 7;
        int tg_s = lane_s & 3, gid_s = lane_s >> 2;
        int j  = 8*nt + gid_s;
        int da = 8*ks + tg_s;
        float v0 = 0.f, v1 = 0.f;
        if (j < 10)      { v0 = W_pi[da*10 + j];        v1 = W_pi[(da+4)*10 + j]; }
        else if (j < 20) { v0 = W_sg[da*10 + (j-10)];   v1 = W_sg[(da+4)*10 + (j-10)]; }
        else if (j < 30) { v0 = W_mu[da*10 + (j-20)];   v1 = W_mu[(da+4)*10 + (j-20)]; }
        uint2 q; q.x = cvt_tf32(v0); q.y = cvt_tf32(v1);
        Bs[s] = q;
    }
    if (tid < 10) {
        bias[tid     ] = b_pi[tid];
        bias[tid + 10] = b_sg[tid];
        bias[tid + 20] = b_mu[tid];
    }
    __syncthreads();

    const int lane = tid & 31, wid = tid >> 5;
    const int tg = lane & 3, gid = lane >> 2;
    const int pbase = wid * 32;
    const float2* __restrict__ gw = g_w + (size_t)b * DD * NP;

    float C[2][2][4][4];
    #pragma unroll
    for (int l = 0; l < 2; l++)
        #pragma unroll
        for (int mt = 0; mt < 2; mt++)
            #pragma unroll
            for (int nt = 0; nt < 4; nt++)
                #pragma unroll
                for (int r = 0; r < 4; r++) C[l][mt][nt][r] = 0.f;

    // ---- software-pipelined mainloop: prefetch ks+1's w while MMA'ing ks ----
    float2 w0[4], w1[4];
    {
        const int d0 = tg, d1 = tg + 4;
        #pragma unroll
        for (int r = 0; r < 4; r++) {
            int p = pbase + 8*r + gid;
            w0[r] = gw[d0*NP + p];
            w1[r] = gw[d1*NP + p];
        }
    }

    #pragma unroll 1
    for (int ks = 0; ks < 16; ks++) {
        // prefetch next chunk (guarded index, no OOB)
        float2 n0[4], n1[4];
        const int ksn = (ks < 15) ? ks + 1 : 15;
        {
            const int d0 = 8*ksn + tg, d1 = d0 + 4;
            #pragma unroll
            for (int r = 0; r < 4; r++) {
                int p = pbase + 8*r + gid;
                n0[r] = gw[d0*NP + p];
                n1[r] = gw[d1*NP + p];
            }
        }

        const int d0 = 8*ks + tg, d1 = d0 + 4;
        float2 u00 = ueu_s[d0],      u01 = ueu_s[d1];
        float2 u10 = ueu_s[DD + d0], u11 = ueu_s[DD + d1];
        uint32_t bb[4][2];
        #pragma unroll
        for (int nt = 0; nt < 4; nt++) {
            uint2 q = Bs[((ks*4 + nt) << 5) + lane];
            bb[nt][0] = q.x; bb[nt][1] = q.y;
        }

        #pragma unroll
        for (int l = 0; l < 2; l++) {
            float2 ua = l ? u10 : u00;
            float2 ub = l ? u11 : u01;
            #pragma unroll
            for (int mt = 0; mt < 2; mt++) {
                uint32_t a[4];
                a[0] = cvt_tf32(elu2(ua, w0[mt*2 + 0]));
                a[1] = cvt_tf32(elu2(ua, w0[mt*2 + 1]));
                a[2] = cvt_tf32(elu2(ub, w1[mt*2 + 0]));
                a[3] = cvt_tf32(elu2(ub, w1[mt*2 + 1]));
                #pragma unroll
                for (int nt = 0; nt < 4; nt++)
                    mma8(C[l][mt][nt], a, bb[nt]);
            }
        }

        #pragma unroll
        for (int r = 0; r < 4; r++) { w0[r] = n0[r]; w1[r] = n1[r]; }
    }

    // ---- per-l: scatter -> epilogue (Csm holds one l at a time) ----
    const int p  = tid;
    const int mp = (p < num_p[b]);
    const int nl = num_l[b];
    const float4 xp = g_xp[b * NP + p];

    #pragma unroll
    for (int l = 0; l < 2; l++) {
        #pragma unroll
        for (int mt = 0; mt < 2; mt++)
            #pragma unroll
            for (int nt = 0; nt < 4; nt++) {
                int prow = pbase + mt*16 + gid;
                int col  = 8*nt + 2*tg;
                *(float2*)&Csm[prow*CPAD + col]     = make_float2(C[l][mt][nt][0], C[l][mt][nt][1]);
                *(float2*)&Csm[(prow+8)*CPAD + col] = make_float2(C[l][mt][nt][2], C[l][mt][nt][3]);
            }
        __syncthreads();

        const int bl = bl0 + l;
        const float m = (l0 + l < nl && mp) ? 1.f : 0.f;
        epi_l(Csm, bias, bl, p, m, xp, g_xl[bl], out);

        if (l == 0) __syncthreads();   // protect Csm before l=1 scatter
    }
}

extern "C" void kernel_launch(void* const* d_in, const int* in_sizes, int n_in,
                              void* d_out, int out_size)
{
    int s = 0;
    if (n_in >= 20 && in_sizes[6] == 1 && in_sizes[7] == 1) s = 2;

    const float* hl    = (const float*)d_in[0];
    const float* hp    = (const float*)d_in[1];
    const float* pos_l = (const float*)d_in[2];
    const float* pos_p = (const float*)d_in[3];
    const int*   num_l = (const int*)  d_in[4];
    const int*   num_p = (const int*)  d_in[5];
    const float* W1    = (const float*)d_in[6 + s];
    const float* b1    = (const float*)d_in[7 + s];
    const float* gamma = (const float*)d_in[8 + s];
    const float* beta  = (const float*)d_in[9 + s];
    const float* mean  = (const float*)d_in[10 + s];
    const float* var   = (const float*)d_in[11 + s];
    const float* W_pi  = (const float*)d_in[12 + s];
    const float* b_pi  = (const float*)d_in[13 + s];
    const float* W_sg  = (const float*)d_in[14 + s];
    const float* b_sg  = (const float*)d_in[15 + s];
    const float* W_mu  = (const float*)d_in[16 + s];
    const float* b_mu  = (const float*)d_in[17 + s];
    float* out = (float*)d_out;

    cudaFuncSetAttribute(k_main, cudaFuncAttributeMaxDynamicSharedMemorySize, SM_TOTAL);

    k_pre <<<NROW_L/8 + NROW_P/8, DD>>>(hl, hp, pos_l, pos_p, num_l, num_p,
                                        W1, b1, gamma, beta, mean, var);
    k_main<<<BB * NL / 2, 256, SM_TOTAL>>>(W_pi, b_pi, W_sg, b_sg, W_mu, b_mu,
                                           num_l, num_p, out);
}

// round 11
// speedup vs baseline: 1.4362x; 1.4362x over previous
#include <cuda_runtime.h>
#include <stdint.h>
#include <math.h>

#define BB 16
#define NL 48
#define NP 256
#define DD 128
#define NROW_L (BB*NL)    /* 768  */
#define NROW_P (BB*NP)    /* 4096 */
#define NPAIR  (BB*NL*NP) /* 196608 */

#define PI_OFF 0
#define SG_OFF (NPAIR*10)
#define MU_OFF (NPAIR*20)
#define DI_OFF (NPAIR*30)
#define CM_OFF (NPAIR*31)

// ---- dynamic smem layout for k_main ----
#define CPAD   34
#define WROW   258                         /* padded row stride in float2 (256+2) */
#define WSTGF2 (8*WROW)                    /* one stage: 2064 float2 = 16512 B   */
#define SM_UEU   0                         /* float2[256]        2048 B  */
#define SM_BS    2048                      /* uint2[2048]       16384 B  */
#define SM_WST   (2048+16384)              /* 2 stages          33024 B  */
#define SM_CSM   (2048+16384+33024)        /* float[256*34]     34816 B  */
#define SM_BIAS  (2048+16384+33024+34816)  /* float[32]           128 B  */
#define SM_TOTAL (2048+16384+33024+34816+128)  /* 86400 B */

__device__ float2 g_ueu[NROW_L*DD];   // {u, exp(u)} per (b,l,d)
__device__ float2 g_w  [BB*DD*NP];    // [b][d][p] {v, exp(v)}
__device__ float4 g_xl [NROW_L];
__device__ float4 g_xp [NROW_P];

__device__ __forceinline__ uint32_t cvt_tf32(float f) {
    uint32_t r;
    asm("cvt.rna.tf32.f32 %0, %1;" : "=r"(r) : "f"(f));
    return r;
}
__device__ __forceinline__ void mma8(float* c, const uint32_t* a, const uint32_t* b) {
    asm("mma.sync.aligned.m16n8k8.row.col.f32.tf32.tf32.f32 "
        "{%0,%1,%2,%3}, {%4,%5,%6,%7}, {%8,%9}, {%0,%1,%2,%3};"
        : "+f"(c[0]), "+f"(c[1]), "+f"(c[2]), "+f"(c[3])
        : "r"(a[0]), "r"(a[1]), "r"(a[2]), "r"(a[3]), "r"(b[0]), "r"(b[1]));
}
__device__ __forceinline__ float elu2(float2 u, float2 w) {
    float uv = u.x + w.x;
    float t  = fmaf(u.y, w.y, -1.f);
    return (uv > 0.f) ? uv : t;
}
__device__ __forceinline__ unsigned smem_u32(const void* p) {
    return (unsigned)__cvta_generic_to_shared(p);
}
#define CP_ASYNC16(dst, src) \
    asm volatile("cp.async.ca.shared.global [%0], [%1], 16;" :: "r"(dst), "l"(src))
#define CP_COMMIT() asm volatile("cp.async.commit_group;")
#define CP_WAIT1()  asm volatile("cp.async.wait_group 1;")
#define CP_WAIT0()  asm volatile("cp.async.wait_group 0;")

// ---------------- fused prep (unchanged) ----------------
__global__ __launch_bounds__(DD) void k_pre(
    const float* __restrict__ hl, const float* __restrict__ hp,
    const float* __restrict__ pos_l, const float* __restrict__ pos_p,
    const int* __restrict__ num_l, const int* __restrict__ num_p,
    const float* __restrict__ W1, const float* __restrict__ b1,
    const float* __restrict__ gamma, const float* __restrict__ beta,
    const float* __restrict__ mean, const float* __restrict__ var)
{
    __shared__ int cl[BB+1], cp[BB+1];
    __shared__ float xs[8][DD];
    __shared__ float2 tt[DD][9];
    const int tid = threadIdx.x;

    if (tid == 0) {
        cl[0] = 0; cp[0] = 0;
        #pragma unroll
        for (int i = 0; i < BB; i++) { cl[i+1] = cl[i] + num_l[i]; cp[i+1] = cp[i] + num_p[i]; }
    }
    __syncthreads();

    const float kf = gamma[tid] * rsqrtf(var[tid] + 1e-5f);

    if (blockIdx.x < NROW_L/8) {
        const int r0 = blockIdx.x * 8;
        const int b  = r0 / NL, l0 = r0 % NL;
        const int nl = num_l[b];
        #pragma unroll
        for (int i = 0; i < 8; i++) {
            float v = 0.f;
            if (l0 + i < nl) v = hl[(cl[b] + l0 + i) * DD + tid];
            xs[i][tid] = v;
        }
        __syncthreads();
        float acc[8] = {0,0,0,0,0,0,0,0};
        #pragma unroll 4
        for (int d = 0; d < DD; d++) {
            float w = W1[d * DD + tid];
            #pragma unroll
            for (int i = 0; i < 8; i++) acc[i] = fmaf(xs[i][d], w, acc[i]);
        }
        const float c = (b1[tid] - mean[tid]) * kf + beta[tid];
        #pragma unroll
        for (int i = 0; i < 8; i++) {
            float u = fmaf(acc[i], kf, c);
            g_ueu[(r0 + i) * DD + tid] = make_float2(u, __expf(u));
        }
        if (tid < 8) {
            int l = l0 + tid;
            float4 o = make_float4(0.f, 0.f, 0.f, 0.f);
            if (l < nl) {
                int s = cl[b] + l;
                float x = pos_l[s*3+0], y = pos_l[s*3+1], z = pos_l[s*3+2];
                o = make_float4(x, y, z, x*x + y*y + z*z);
            }
            g_xl[r0 + tid] = o;
        }
    } else {
        const int r0 = (blockIdx.x - NROW_L/8) * 8;
        const int b  = r0 / NP, p0 = r0 % NP;
        const int np = num_p[b];
        #pragma unroll
        for (int i = 0; i < 8; i++) {
            float v = 0.f;
            if (p0 + i < np) v = hp[(cp[b] + p0 + i) * DD + tid];
            xs[i][tid] = v;
        }
        __syncthreads();
        float acc[8] = {0,0,0,0,0,0,0,0};
        const float* W1b = W1 + DD * DD;
        #pragma unroll 4
        for (int d = 0; d < DD; d++) {
            float w = W1b[d * DD + tid];
            #pragma unroll
            for (int i = 0; i < 8; i++) acc[i] = fmaf(xs[i][d], w, acc[i]);
        }
        #pragma unroll
        for (int i = 0; i < 8; i++) {
            float v = acc[i] * kf;
            tt[tid][i] = make_float2(v, __expf(v));
        }
        __syncthreads();
        #pragma unroll
        for (int it = 0; it < 8; it++) {
            int idx = tid + DD * it;
            int f = idx >> 3, pl = idx & 7;
            g_w[(b * DD + f) * NP + p0 + pl] = tt[f][pl];
        }
        if (tid < 8) {
            int p = p0 + tid;
            float4 o = make_float4(0.f, 0.f, 0.f, 0.f);
            if (p < np) {
                int s = cp[b] + p;
                float x = pos_p[s*3+0], y = pos_p[s*3+1], z = pos_p[s*3+2];
                o = make_float4(x, y, z, x*x + y*y + z*z);
            }
            g_xp[r0 + tid] = o;
        }
    }
}

// ---------------- epilogue for one l-row (reads Csm), per-p ----------------
__device__ __forceinline__ void epi_l(
    const float* __restrict__ Csm, const float* __restrict__ bias,
    int bl, int p, float m, float4 xp, float4 xl, float* __restrict__ out)
{
    const float* row = &Csm[p * CPAD];
    float z[30];
    #pragma unroll
    for (int jj = 0; jj < 15; jj++) {
        float2 q = *(const float2*)&row[2*jj];
        z[2*jj] = q.x; z[2*jj+1] = q.y;
    }

    float zmax = -1e30f;
    #pragma unroll
    for (int j = 0; j < 10; j++) { z[j] += bias[j]; zmax = fmaxf(zmax, z[j]); }
    float ssum = 0.f;
    #pragma unroll
    for (int j = 0; j < 10; j++) { float e = __expf(z[j] - zmax); z[j] = e; ssum += e; }
    float inv = m / ssum;

    const int base = (bl * NP + p) * 10;
    float2* opi = (float2*)(out + PI_OFF + base);
    float2* osg = (float2*)(out + SG_OFF + base);
    float2* omu = (float2*)(out + MU_OFF + base);
    #pragma unroll
    for (int j = 0; j < 5; j++)
        opi[j] = make_float2(z[2*j] * inv, z[2*j+1] * inv);
    #pragma unroll
    for (int j = 0; j < 10; j++) {
        float t = z[10 + j] + bias[10 + j];
        float e = (t > 0.f) ? t : (__expf(t) - 1.f);
        z[10 + j] = (e + 1.1f) * m;
    }
    #pragma unroll
    for (int j = 0; j < 5; j++) osg[j] = make_float2(z[10+2*j], z[11+2*j]);
    #pragma unroll
    for (int j = 0; j < 10; j++) {
        float t = z[20 + j] + bias[20 + j];
        float e = (t > 0.f) ? t : (__expf(t) - 1.f);
        z[20 + j] = (e + 1.0f) * m;
    }
    #pragma unroll
    for (int j = 0; j < 5; j++) omu[j] = make_float2(z[20+2*j], z[21+2*j]);

    float d2 = xl.w + xp.w - 2.f * (xl.x*xp.x + xl.y*xp.y + xl.z*xp.z);
    out[DI_OFF + bl * NP + p] = sqrtf(fmaxf(d2, 0.f)) * m;
    out[CM_OFF + bl * NP + p] = m;
}

// ---------------- main: tf32 MMA + cp.async double-buffered g_w ----------------
__global__ __launch_bounds__(256, 2) void k_main(
    const float* __restrict__ W_pi, const float* __restrict__ b_pi,
    const float* __restrict__ W_sg, const float* __restrict__ b_sg,
    const float* __restrict__ W_mu, const float* __restrict__ b_mu,
    const int* __restrict__ num_l, const int* __restrict__ num_p,
    float* __restrict__ out)
{
    extern __shared__ char smem[];
    float2* ueu_s = (float2*)(smem + SM_UEU);
    uint2*  Bs    = (uint2*)(smem + SM_BS);
    float2* Wst   = (float2*)(smem + SM_WST);   // 2 stages of [8][WROW]
    float*  Csm   = (float*)(smem + SM_CSM);
    float*  bias  = (float*)(smem + SM_BIAS);

    const int tid = threadIdx.x;
    const int bl0 = blockIdx.x * 2;
    const int b   = bl0 / NL;
    const int l0  = bl0 % NL;

    ueu_s[tid] = g_ueu[bl0 * DD + tid];

    for (int s = tid; s < 2048; s += 256) {
        int lane_s = s & 31, nt = (s >> 5) & 3, ks = s >> 7;
        int tg_s = lane_s & 3, gid_s = lane_s >> 2;
        int j  = 8*nt + gid_s;
        int da = 8*ks + tg_s;
        float v0 = 0.f, v1 = 0.f;
        if (j < 10)      { v0 = W_pi[da*10 + j];        v1 = W_pi[(da+4)*10 + j]; }
        else if (j < 20) { v0 = W_sg[da*10 + (j-10)];   v1 = W_sg[(da+4)*10 + (j-10)]; }
        else if (j < 30) { v0 = W_mu[da*10 + (j-20)];   v1 = W_mu[(da+4)*10 + (j-20)]; }
        uint2 q; q.x = cvt_tf32(v0); q.y = cvt_tf32(v1);
        Bs[s] = q;
    }
    if (tid < 10) {
        bias[tid     ] = b_pi[tid];
        bias[tid + 10] = b_sg[tid];
        bias[tid + 20] = b_mu[tid];
    }

    const int lane = tid & 31, wid = tid >> 5;
    const int tg = lane & 3, gid = lane >> 2;
    const int pbase = wid * 32;
    const float2* __restrict__ gw = g_w + (size_t)b * DD * NP;

    // cp.async staging: thread copies 64B of row (tid>>5), cols [(tid&31)*8 ..)
    const int c_dl  = tid >> 5;          // 0..7 local d-row
    const int c_off = (tid & 31) * 8;    // float2 offset within row
    const unsigned wst_base = smem_u32(Wst);

    // prologue: stage ks=0 into buf 0
    {
        const float2* src = gw + c_dl * NP + c_off;
        unsigned dst = wst_base + (unsigned)(c_dl * WROW + c_off) * 8u;
        #pragma unroll
        for (int i = 0; i < 4; i++) CP_ASYNC16(dst + 16u*i, (const void*)(src + 2*i));
        CP_COMMIT();
    }
    __syncthreads();   // also covers ueu_s/Bs/bias init

    float C[2][2][4][4];
    #pragma unroll
    for (int l = 0; l < 2; l++)
        #pragma unroll
        for (int mt = 0; mt < 2; mt++)
            #pragma unroll
            for (int nt = 0; nt < 4; nt++)
                #pragma unroll
                for (int r = 0; r < 4; r++) C[l][mt][nt][r] = 0.f;

    #pragma unroll 1
    for (int ks = 0; ks < 16; ks++) {
        // issue next stage (dup of 15 on last iter — target buffer unused after)
        const int ksn = (ks < 15) ? ks + 1 : 15;
        {
            const float2* src = gw + (8*ksn + c_dl) * NP + c_off;
            unsigned dst = wst_base
                         + (unsigned)(((ks+1)&1) * WSTGF2 + c_dl * WROW + c_off) * 8u;
            #pragma unroll
            for (int i = 0; i < 4; i++) CP_ASYNC16(dst + 16u*i, (const void*)(src + 2*i));
            CP_COMMIT();
        }
        CP_WAIT1();        // stage ks has landed
        __syncthreads();   // visible block-wide

        const int d0 = 8*ks + tg, d1 = d0 + 4;
        float2 u00 = ueu_s[d0],      u01 = ueu_s[d1];
        float2 u10 = ueu_s[DD + d0], u11 = ueu_s[DD + d1];
        uint32_t bb[4][2];
        #pragma unroll
        for (int nt = 0; nt < 4; nt++) {
            uint2 q = Bs[((ks*4 + nt) << 5) + lane];
            bb[nt][0] = q.x; bb[nt][1] = q.y;
        }

        const float2* stg = Wst + (ks & 1) * WSTGF2;
        float2 w0[4], w1[4];
        #pragma unroll
        for (int r = 0; r < 4; r++) {
            int p = pbase + 8*r + gid;
            w0[r] = stg[tg * WROW + p];
            w1[r] = stg[(tg + 4) * WROW + p];
        }

        #pragma unroll
        for (int l = 0; l < 2; l++) {
            float2 ua = l ? u10 : u00;
            float2 ub = l ? u11 : u01;
            #pragma unroll
            for (int mt = 0; mt < 2; mt++) {
                uint32_t a[4];
                a[0] = cvt_tf32(elu2(ua, w0[mt*2 + 0]));
                a[1] = cvt_tf32(elu2(ua, w0[mt*2 + 1]));
                a[2] = cvt_tf32(elu2(ub, w1[mt*2 + 0]));
                a[3] = cvt_tf32(elu2(ub, w1[mt*2 + 1]));
                #pragma unroll
                for (int nt = 0; nt < 4; nt++)
                    mma8(C[l][mt][nt], a, bb[nt]);
            }
        }

        __syncthreads();   // all reads of buf[ks&1] done before it's overwritten
    }
    CP_WAIT0();            // drain outstanding async copies before smem reuse/exit

    // ---- per-l: scatter -> epilogue (Csm holds one l at a time) ----
    const int p  = tid;
    const int mp = (p < num_p[b]);
    const int nl = num_l[b];
    const float4 xp = g_xp[b * NP + p];

    #pragma unroll
    for (int l = 0; l < 2; l++) {
        #pragma unroll
        for (int mt = 0; mt < 2; mt++)
            #pragma unroll
            for (int nt = 0; nt < 4; nt++) {
                int prow = pbase + mt*16 + gid;
                int col  = 8*nt + 2*tg;
                *(float2*)&Csm[prow*CPAD + col]     = make_float2(C[l][mt][nt][0], C[l][mt][nt][1]);
                *(float2*)&Csm[(prow+8)*CPAD + col] = make_float2(C[l][mt][nt][2], C[l][mt][nt][3]);
            }
        __syncthreads();

        const int bl = bl0 + l;
        const float m = (l0 + l < nl && mp) ? 1.f : 0.f;
        epi_l(Csm, bias, bl, p, m, xp, g_xl[bl], out);

        if (l == 0) __syncthreads();
    }
}

extern "C" void kernel_launch(void* const* d_in, const int* in_sizes, int n_in,
                              void* d_out, int out_size)
{
    int s = 0;
    if (n_in >= 20 && in_sizes[6] == 1 && in_sizes[7] == 1) s = 2;

    const float* hl    = (const float*)d_in[0];
    const float* hp    = (const float*)d_in[1];
    const float* pos_l = (const float*)d_in[2];
    const float* pos_p = (const float*)d_in[3];
    const int*   num_l = (const int*)  d_in[4];
    const int*   num_p = (const int*)  d_in[5];
    const float* W1    = (const float*)d_in[6 + s];
    const float* b1    = (const float*)d_in[7 + s];
    const float* gamma = (const float*)d_in[8 + s];
    const float* beta  = (const float*)d_in[9 + s];
    const float* mean  = (const float*)d_in[10 + s];
    const float* var   = (const float*)d_in[11 + s];
    const float* W_pi  = (const float*)d_in[12 + s];
    const float* b_pi  = (const float*)d_in[13 + s];
    const float* W_sg  = (const float*)d_in[14 + s];
    const float* b_sg  = (const float*)d_in[15 + s];
    const float* W_mu  = (const float*)d_in[16 + s];
    const float* b_mu  = (const float*)d_in[17 + s];
    float* out = (float*)d_out;

    cudaFuncSetAttribute(k_main, cudaFuncAttributeMaxDynamicSharedMemorySize, SM_TOTAL);

    k_pre <<<NROW_L/8 + NROW_P/8, DD>>>(hl, hp, pos_l, pos_p, num_l, num_p,
                                        W1, b1, gamma, beta, mean, var);
    k_main<<<BB * NL / 2, 256, SM_TOTAL>>>(W_pi, b_pi, W_sg, b_sg, W_mu, b_mu,
                                           num_l, num_p, out);
}

// round 14
// speedup vs baseline: 1.6923x; 1.1783x over previous
#include <cuda_runtime.h>
#include <cuda_bf16.h>
#include <stdint.h>
#include <math.h>

#define BB 16
#define NL 48
#define NP 256
#define DD 128
#define NROW_L (BB*NL)    /* 768  */
#define NROW_P (BB*NP)    /* 4096 */
#define NPAIR  (BB*NL*NP) /* 196608 */

#define PI_OFF 0
#define SG_OFF (NPAIR*10)
#define MU_OFF (NPAIR*20)
#define DI_OFF (NPAIR*30)
#define CM_OFF (NPAIR*31)

// ---- dynamic smem layout for k_mm ----
#define CPAD 34
#define SM_UEU   0                         /* float2[256]        2048 B */
#define SM_BS    2048                      /* uint2[1024]        8192 B */
#define SM_CSM   (2048+8192)               /* float[256*34]     34816 B */
#define SM_BIAS  (2048+8192+34816)         /* float[32]           128 B */
#define SM_TOTAL (2048+8192+34816+128)     /* 45184 B */

__device__ float2 g_ueu[NROW_L*DD];   // {u, exp(u)} per (b,l,d)
__device__ float4 g_w4 [BB*64*NP];    // [b][dpair][p] = {v_2d, e^v_2d, v_2d+1, e^v_2d+1}
__device__ uint2  g_bfr[1024];        // B fragments [ks][nt][lane] bf16x2 pairs
__device__ float4 g_xl [NROW_L];
__device__ float4 g_xp [NROW_P];

__device__ __forceinline__ uint32_t bf2(float lo, float hi) {
    __nv_bfloat162 h = __float22bfloat162_rn(make_float2(lo, hi));
    return *reinterpret_cast<uint32_t*>(&h);
}
__device__ __forceinline__ void mma16(float* c, const uint32_t* a, const uint32_t* bq) {
    asm("mma.sync.aligned.m16n8k16.row.col.f32.bf16.bf16.f32 "
        "{%0,%1,%2,%3}, {%4,%5,%6,%7}, {%8,%9}, {%0,%1,%2,%3};"
        : "+f"(c[0]), "+f"(c[1]), "+f"(c[2]), "+f"(c[3])
        : "r"(a[0]), "r"(a[1]), "r"(a[2]), "r"(a[3]), "r"(bq[0]), "r"(bq[1]));
}
__device__ __forceinline__ float elu2c(float u, float eu, float v, float ev) {
    float uv = u + v;
    float t  = fmaf(eu, ev, -1.f);
    return (uv > 0.f) ? uv : t;
}
__device__ __forceinline__ float wsel(const float* __restrict__ W_pi,
                                      const float* __restrict__ W_sg,
                                      const float* __restrict__ W_mu,
                                      int d, int n) {
    if (n < 10)      return W_pi[d*10 + n];
    else if (n < 20) return W_sg[d*10 + n - 10];
    else if (n < 30) return W_mu[d*10 + n - 20];
    return 0.f;
}

// ---------------- fused prep + B-fragment builder ----------------
__global__ __launch_bounds__(DD) void k_pre(
    const float* __restrict__ hl, const float* __restrict__ hp,
    const float* __restrict__ pos_l, const float* __restrict__ pos_p,
    const int* __restrict__ num_l, const int* __restrict__ num_p,
    const float* __restrict__ W1, const float* __restrict__ b1,
    const float* __restrict__ gamma, const float* __restrict__ beta,
    const float* __restrict__ mean, const float* __restrict__ var,
    const float* __restrict__ W_pi, const float* __restrict__ W_sg,
    const float* __restrict__ W_mu)
{
    __shared__ int cl[BB+1], cp[BB+1];
    __shared__ float xs[8][DD];
    __shared__ float2 tt[DD][9];
    const int tid = threadIdx.x;

    if (blockIdx.x >= NROW_L/8 + NROW_P/8) {
        // ---- B fragment table: [ks(8)][nt(4)][lane(32)] ----
        #pragma unroll
        for (int it = 0; it < 8; it++) {
            int idx = tid + DD * it;            // 0..1023
            int lane = idx & 31, nt = (idx >> 5) & 3, ks = idx >> 7;
            int tg = lane & 3, gid = lane >> 2;
            int n  = 8*nt + gid;
            int d0 = 16*ks + 2*tg;
            uint2 q;
            q.x = bf2(wsel(W_pi, W_sg, W_mu, d0,     n),
                      wsel(W_pi, W_sg, W_mu, d0 + 1, n));
            q.y = bf2(wsel(W_pi, W_sg, W_mu, d0 + 8, n),
                      wsel(W_pi, W_sg, W_mu, d0 + 9, n));
            g_bfr[idx] = q;
        }
        return;
    }

    if (tid == 0) {
        cl[0] = 0; cp[0] = 0;
        #pragma unroll
        for (int i = 0; i < BB; i++) { cl[i+1] = cl[i] + num_l[i]; cp[i+1] = cp[i] + num_p[i]; }
    }
    __syncthreads();

    const float kf = gamma[tid] * rsqrtf(var[tid] + 1e-5f);

    if (blockIdx.x < NROW_L/8) {
        const int r0 = blockIdx.x * 8;
        const int b  = r0 / NL, l0 = r0 % NL;
        const int nl = num_l[b];
        #pragma unroll
        for (int i = 0; i < 8; i++) {
            float v = 0.f;
            if (l0 + i < nl) v = hl[(cl[b] + l0 + i) * DD + tid];
            xs[i][tid] = v;
        }
        __syncthreads();
        float acc[8] = {0,0,0,0,0,0,0,0};
        #pragma unroll 4
        for (int d = 0; d < DD; d++) {
            float w = W1[d * DD + tid];
            #pragma unroll
            for (int i = 0; i < 8; i++) acc[i] = fmaf(xs[i][d], w, acc[i]);
        }
        const float c = (b1[tid] - mean[tid]) * kf + beta[tid];
        #pragma unroll
        for (int i = 0; i < 8; i++) {
            float u = fmaf(acc[i], kf, c);
            g_ueu[(r0 + i) * DD + tid] = make_float2(u, __expf(u));
        }
        if (tid < 8) {
            int l = l0 + tid;
            float4 o = make_float4(0.f, 0.f, 0.f, 0.f);
            if (l < nl) {
                int s = cl[b] + l;
                float x = pos_l[s*3+0], y = pos_l[s*3+1], z = pos_l[s*3+2];
                o = make_float4(x, y, z, x*x + y*y + z*z);
            }
            g_xl[r0 + tid] = o;
        }
    } else {
        const int r0 = (blockIdx.x - NROW_L/8) * 8;
        const int b  = r0 / NP, p0 = r0 % NP;
        const int np = num_p[b];
        #pragma unroll
        for (int i = 0; i < 8; i++) {
            float v = 0.f;
            if (p0 + i < np) v = hp[(cp[b] + p0 + i) * DD + tid];
            xs[i][tid] = v;
        }
        __syncthreads();
        float acc[8] = {0,0,0,0,0,0,0,0};
        const float* W1b = W1 + DD * DD;
        #pragma unroll 4
        for (int d = 0; d < DD; d++) {
            float w = W1b[d * DD + tid];
            #pragma unroll
            for (int i = 0; i < 8; i++) acc[i] = fmaf(xs[i][d], w, acc[i]);
        }
        #pragma unroll
        for (int i = 0; i < 8; i++) {
            float v = acc[i] * kf;
            tt[tid][i] = make_float2(v, __expf(v));
        }
        __syncthreads();
        #pragma unroll
        for (int it = 0; it < 4; it++) {
            int idx = tid + DD * it;       // 0..511
            int f2 = idx >> 3, pl = idx & 7;
            float2 a = tt[2*f2][pl], c2 = tt[2*f2+1][pl];
            g_w4[((size_t)b*64 + f2)*NP + p0 + pl] = make_float4(a.x, a.y, c2.x, c2.y);
        }
        if (tid < 8) {
            int p = p0 + tid;
            float4 o = make_float4(0.f, 0.f, 0.f, 0.f);
            if (p < np) {
                int s = cp[b] + p;
                float x = pos_p[s*3+0], y = pos_p[s*3+1], z = pos_p[s*3+2];
                o = make_float4(x, y, z, x*x + y*y + z*z);
            }
            g_xp[r0 + tid] = o;
        }
    }
}

// ---------------- epilogue for one l-row (reads Csm), per-p ----------------
__device__ __forceinline__ void epi_l(
    const float* __restrict__ Csm, const float* __restrict__ bias,
    int bl, int p, float m, float4 xp, float4 xl, float* __restrict__ out)
{
    const float* row = &Csm[p * CPAD];
    float z[30];
    #pragma unroll
    for (int jj = 0; jj < 15; jj++) {
        float2 q = *(const float2*)&row[2*jj];
        z[2*jj] = q.x; z[2*jj+1] = q.y;
    }

    float zmax = -1e30f;
    #pragma unroll
    for (int j = 0; j < 10; j++) { z[j] += bias[j]; zmax = fmaxf(zmax, z[j]); }
    float ssum = 0.f;
    #pragma unroll
    for (int j = 0; j < 10; j++) { float e = __expf(z[j] - zmax); z[j] = e; ssum += e; }
    float inv = m / ssum;

    const int base = (bl * NP + p) * 10;
    float2* opi = (float2*)(out + PI_OFF + base);
    float2* osg = (float2*)(out + SG_OFF + base);
    float2* omu = (float2*)(out + MU_OFF + base);
    #pragma unroll
    for (int j = 0; j < 5; j++)
        opi[j] = make_float2(z[2*j] * inv, z[2*j+1] * inv);
    #pragma unroll
    for (int j = 0; j < 10; j++) {
        float t = z[10 + j] + bias[10 + j];
        float e = (t > 0.f) ? t : (__expf(t) - 1.f);
        z[10 + j] = (e + 1.1f) * m;
    }
    #pragma unroll
    for (int j = 0; j < 5; j++) osg[j] = make_float2(z[10+2*j], z[11+2*j]);
    #pragma unroll
    for (int j = 0; j < 10; j++) {
        float t = z[20 + j] + bias[20 + j];
        float e = (t > 0.f) ? t : (__expf(t) - 1.f);
        z[20 + j] = (e + 1.0f) * m;
    }
    #pragma unroll
    for (int j = 0; j < 5; j++) omu[j] = make_float2(z[20+2*j], z[21+2*j]);

    float d2 = xl.w + xp.w - 2.f * (xl.x*xp.x + xl.y*xp.y + xl.z*xp.z);
    out[DI_OFF + bl * NP + p] = sqrtf(fmaxf(d2, 0.f)) * m;
    out[CM_OFF + bl * NP + p] = m;
}

// ---------------- main: bf16 m16n8k16 MMA, 2 l-rows per block ----------------
__global__ __launch_bounds__(256, 2) void k_mm(
    const float* __restrict__ b_pi, const float* __restrict__ b_sg,
    const float* __restrict__ b_mu,
    const int* __restrict__ num_l, const int* __restrict__ num_p,
    float* __restrict__ out)
{
    extern __shared__ char smem[];
    float2* ueu_s = (float2*)(smem + SM_UEU);   // [2][128] {u, eu}
    uint2*  Bs    = (uint2*)(smem + SM_BS);     // [8 ks][4 nt][32 lane]
    float*  Csm   = (float*)(smem + SM_CSM);    // [256][CPAD]
    float*  bias  = (float*)(smem + SM_BIAS);

    const int tid = threadIdx.x;
    const int bl0 = blockIdx.x * 2;
    const int b   = bl0 / NL;
    const int l0  = bl0 % NL;

    ueu_s[tid] = g_ueu[bl0 * DD + tid];
    #pragma unroll
    for (int i = 0; i < 4; i++) Bs[tid + 256*i] = g_bfr[tid + 256*i];
    if (tid < 10) {
        bias[tid     ] = b_pi[tid];
        bias[tid + 10] = b_sg[tid];
        bias[tid + 20] = b_mu[tid];
    }
    __syncthreads();

    const int lane = tid & 31, wid = tid >> 5;
    const int tg = lane & 3, gid = lane >> 2;
    const int pbase = wid * 32;
    const float4* __restrict__ gw = g_w4 + (size_t)b * 64 * NP;

    float C[2][2][4][4];
    #pragma unroll
    for (int l = 0; l < 2; l++)
        #pragma unroll
        for (int mt = 0; mt < 2; mt++)
            #pragma unroll
            for (int nt = 0; nt < 4; nt++)
                #pragma unroll
                for (int r = 0; r < 4; r++) C[l][mt][nt][r] = 0.f;

    #pragma unroll 1
    for (int ks = 0; ks < 8; ks++) {
        const int d0  = 16*ks + 2*tg;           // ueu index (element)
        const int dp0 = 8*ks + tg;              // g_w4 d-pair index
        const int dp1 = dp0 + 4;

        // u data for both l rows: {u(d0),eu(d0),u(d0+1),eu(d0+1)} and +8
        float4 uA0 = *(const float4*)&ueu_s[d0];
        float4 uA1 = *(const float4*)&ueu_s[d0 + 8];
        float4 uB0 = *(const float4*)&ueu_s[DD + d0];
        float4 uB1 = *(const float4*)&ueu_s[DD + d0 + 8];

        // B fragments
        uint32_t bq[4][2];
        #pragma unroll
        for (int nt = 0; nt < 4; nt++) {
            uint2 q = Bs[(ks*4 + nt)*32 + lane];
            bq[nt][0] = q.x; bq[nt][1] = q.y;
        }

        #pragma unroll
        for (int mt = 0; mt < 2; mt++) {
            const int p0 = pbase + 16*mt + gid;
            const int p1 = p0 + 8;
            // w values (shared across both l rows)
            float4 wA = __ldg(&gw[(size_t)dp0 * NP + p0]);   // d0, d0+1 @ p0
            float4 wB = __ldg(&gw[(size_t)dp0 * NP + p1]);   // d0, d0+1 @ p1
            float4 wC = __ldg(&gw[(size_t)dp1 * NP + p0]);   // d0+8, d0+9 @ p0
            float4 wD = __ldg(&gw[(size_t)dp1 * NP + p1]);

            #pragma unroll
            for (int l = 0; l < 2; l++) {
                float4 u0 = l ? uB0 : uA0;
                float4 u1 = l ? uB1 : uA1;
                uint32_t a[4];
                a[0] = bf2(elu2c(u0.x, u0.y, wA.x, wA.y),
                           elu2c(u0.z, u0.w, wA.z, wA.w));
                a[1] = bf2(elu2c(u0.x, u0.y, wB.x, wB.y),
                           elu2c(u0.z, u0.w, wB.z, wB.w));
                a[2] = bf2(elu2c(u1.x, u1.y, wC.x, wC.y),
                           elu2c(u1.z, u1.w, wC.z, wC.w));
                a[3] = bf2(elu2c(u1.x, u1.y, wD.x, wD.y),
                           elu2c(u1.z, u1.w, wD.z, wD.w));
                #pragma unroll
                for (int nt = 0; nt < 4; nt++)
                    mma16(C[l][mt][nt], a, bq[nt]);
            }
        }
    }

    // ---- per-l: scatter -> epilogue (Csm holds one l at a time) ----
    const int p  = tid;
    const int mp = (p < num_p[b]);
    const int nl = num_l[b];
    const float4 xp = g_xp[b * NP + p];

    #pragma unroll
    for (int l = 0; l < 2; l++) {
        #pragma unroll
        for (int mt = 0; mt < 2; mt++)
            #pragma unroll
            for (int nt = 0; nt < 4; nt++) {
                int prow = pbase + mt*16 + gid;
                int col  = 8*nt + 2*tg;
                *(float2*)&Csm[prow*CPAD + col]     = make_float2(C[l][mt][nt][0], C[l][mt][nt][1]);
                *(float2*)&Csm[(prow+8)*CPAD + col] = make_float2(C[l][mt][nt][2], C[l][mt][nt][3]);
            }
        __syncthreads();

        const int bl = bl0 + l;
        const float m = (l0 + l < nl && mp) ? 1.f : 0.f;
        epi_l(Csm, bias, bl, p, m, xp, g_xl[bl], out);

        if (l == 0) __syncthreads();
    }
}

extern "C" void kernel_launch(void* const* d_in, const int* in_sizes, int n_in,
                              void* d_out, int out_size)
{
    int s = 0;
    if (n_in >= 20 && in_sizes[6] == 1 && in_sizes[7] == 1) s = 2;

    const float* hl    = (const float*)d_in[0];
    const float* hp    = (const float*)d_in[1];
    const float* pos_l = (const float*)d_in[2];
    const float* pos_p = (const float*)d_in[3];
    const int*   num_l = (const int*)  d_in[4];
    const int*   num_p = (const int*)  d_in[5];
    const float* W1    = (const float*)d_in[6 + s];
    const float* b1    = (const float*)d_in[7 + s];
    const float* gamma = (const float*)d_in[8 + s];
    const float* beta  = (const float*)d_in[9 + s];
    const float* mean  = (const float*)d_in[10 + s];
    const float* var   = (const float*)d_in[11 + s];
    const float* W_pi  = (const float*)d_in[12 + s];
    const float* b_pi  = (const float*)d_in[13 + s];
    const float* W_sg  = (const float*)d_in[14 + s];
    const float* b_sg  = (const float*)d_in[15 + s];
    const float* W_mu  = (const float*)d_in[16 + s];
    const float* b_mu  = (const float*)d_in[17 + s];
    float* out = (float*)d_out;

    cudaFuncSetAttribute(k_mm, cudaFuncAttributeMaxDynamicSharedMemorySize, SM_TOTAL);

    k_pre<<<NROW_L/8 + NROW_P/8 + 1, DD>>>(hl, hp, pos_l, pos_p, num_l, num_p,
                                           W1, b1, gamma, beta, mean, var,
                                           W_pi, W_sg, W_mu);
    k_mm<<<BB * NL / 2, 256, SM_TOTAL>>>(b_pi, b_sg, b_mu, num_l, num_p, out);
}